// round 11
// baseline (speedup 1.0000x reference)
#include <cuda_runtime.h>
#include <cuda_bf16.h>
#include <math.h>

// Problem constants
#define B_   128
#define T_   2048
#define F_   512
#define OS_  20
#define OF_  42
#define NC_  10
#define NCHUNK_ 8
#define CHUNK_  256   // NCHUNK_*CHUNK_ == T_
#define NCOL_ (B_ * OS_)   // 2560
#define KSPLIT_ 16
#define KSL_ (F_ / KSPLIT_)   // 32
#define COLB_ 64

// -------- device scratch (no allocation allowed) --------
__device__ float g_partial[B_ * NCHUNK_ * F_];    // 2 MB
__device__ float g_xC[NCOL_ * F_];                // [col][f]
__device__ float g_p1[KSPLIT_ * OF_ * NCOL_];     // l1 K-split partials (6.9MB)
__device__ float g_bns[B_ * F_];
__device__ float g_bnss[B_ * F_];

// ============================================================
// Kernel 1: partial column sums of y over t in [chunk] ∩ [0, fs)
// ============================================================
__global__ void k_pool_partial(const float* __restrict__ y,
                               const int*   __restrict__ lengths) {
    const int c = blockIdx.x;
    const int b = blockIdx.y;
    const int tid = threadIdx.x;

    const int fs = lengths[b] - (OS_ - 1);
    int t0 = c * CHUNK_;
    int t1 = min(t0 + CHUNK_, fs);

    const float4* row = reinterpret_cast<const float4*>(y + (size_t)b * T_ * F_);
    const int rstride = F_ / 4;

    float4 acc = make_float4(0.f, 0.f, 0.f, 0.f);
    int t = t0;
    for (; t + 8 <= t1; t += 8) {
        float4 v0 = __ldcs(&row[(t + 0) * rstride + tid]);
        float4 v1 = __ldcs(&row[(t + 1) * rstride + tid]);
        float4 v2 = __ldcs(&row[(t + 2) * rstride + tid]);
        float4 v3 = __ldcs(&row[(t + 3) * rstride + tid]);
        float4 v4 = __ldcs(&row[(t + 4) * rstride + tid]);
        float4 v5 = __ldcs(&row[(t + 5) * rstride + tid]);
        float4 v6 = __ldcs(&row[(t + 6) * rstride + tid]);
        float4 v7 = __ldcs(&row[(t + 7) * rstride + tid]);
        acc.x += v0.x; acc.y += v0.y; acc.z += v0.z; acc.w += v0.w;
        acc.x += v1.x; acc.y += v1.y; acc.z += v1.z; acc.w += v1.w;
        acc.x += v2.x; acc.y += v2.y; acc.z += v2.z; acc.w += v2.w;
        acc.x += v3.x; acc.y += v3.y; acc.z += v3.z; acc.w += v3.w;
        acc.x += v4.x; acc.y += v4.y; acc.z += v4.z; acc.w += v4.w;
        acc.x += v5.x; acc.y += v5.y; acc.z += v5.z; acc.w += v5.w;
        acc.x += v6.x; acc.y += v6.y; acc.z += v6.z; acc.w += v6.w;
        acc.x += v7.x; acc.y += v7.y; acc.z += v7.z; acc.w += v7.w;
    }
    for (; t < t1; ++t) {
        float4 v = __ldcs(&row[t * rstride + tid]);
        acc.x += v.x; acc.y += v.y; acc.z += v.z; acc.w += v.w;
    }

    float4* out = reinterpret_cast<float4*>(g_partial + (size_t)(b * NCHUNK_ + c) * F_);
    out[tid] = acc;
}

// ============================================================
// Kernel 2: finish pooling -> g_xC[col][f] (coalesced) + BN partials.
// ============================================================
__global__ void __launch_bounds__(512, 1)
k_pool_finish(const float* __restrict__ y,
              const int*   __restrict__ lengths) {
    const int b = blockIdx.x;
    const int f = threadIdx.x;

    const int fs = lengths[b] - (OS_ - 1);
    const float inv = 1.0f / (float)fs;

    float base = 0.f;
#pragma unroll
    for (int c = 0; c < NCHUNK_; ++c)
        base += g_partial[(size_t)(b * NCHUNK_ + c) * F_ + f];

    const float* yb = y + (size_t)b * T_ * F_ + f;

    float vals[OS_];
    float run = base;
    float s = 0.f, ss = 0.f;
    vals[0] = run * inv;
    s += vals[0]; ss = fmaf(vals[0], vals[0], ss);
#pragma unroll
    for (int j = 1; j < OS_; ++j) {
        run += yb[(size_t)(fs + j - 1) * F_] - yb[(size_t)(j - 1) * F_];
        float v = run * inv;
        vals[j] = v;
        s += v; ss = fmaf(v, v, ss);
    }
    g_bns [b * F_ + f] = s;
    g_bnss[b * F_ + f] = ss;

#pragma unroll
    for (int j = 0; j < OS_; ++j)
        g_xC[(size_t)(b * OS_ + j) * F_ + f] = vals[j];
}

// ============================================================
// Kernel 3: layer 1 GEMM with in-block BN-stat reduction.
// grid (40 colblocks x 64 cols, 16 kslices of 32), block 224.
// 4 blocks/SM -> 640 blocks all resident (single wave).
// thread tile: 6 rows x 2 cols, K vectorized 4x both operands.
// ============================================================
__global__ void __launch_bounds__(224, 4)
k_l1(const float* __restrict__ W1,
     const float* __restrict__ gamma,
     const float* __restrict__ beta) {
    __shared__ float ws[OF_ * KSL_];       // 42x32
    __shared__ float xs[KSL_ * 68];        // [k][col], stride 68
    __shared__ float sS[7 * 32];
    __shared__ float sQ[7 * 32];
    __shared__ float scl[32];
    __shared__ float shf[32];

    const int tid  = threadIdx.x;
    const int lane = tid & 31;
    const int ty   = tid >> 5;             // 0..6
    const int col0 = blockIdx.x * COLB_;
    const int k0   = blockIdx.y * KSL_;

    // BN-stat partials for this 32-channel slice: warp sg, lane = f
    {
        const int sg = ty;                 // 0..6
        float s = 0.f, q = 0.f;
        for (int b = sg; b < B_; b += 7) {
            s += g_bns [b * F_ + k0 + lane];
            q += g_bnss[b * F_ + k0 + lane];
        }
        sS[sg * 32 + lane] = s;
        sQ[sg * 32 + lane] = q;
    }
    // stage W slice (42 x 8 float4)
    {
        const float4* wg = reinterpret_cast<const float4*>(W1);
        float4* wsm = reinterpret_cast<float4*>(ws);
        for (int i = tid; i < OF_ * 8; i += 224) {
            int r = i >> 3, k4 = i & 7;
            wsm[r * 8 + k4] = wg[r * 128 + (k0 >> 2) + k4];
        }
    }
    __syncthreads();

    if (tid < 32) {
        float s = 0.f, q = 0.f;
#pragma unroll
        for (int sg = 0; sg < 7; ++sg) { s += sS[sg * 32 + tid]; q += sQ[sg * 32 + tid]; }
        const float n = (float)(B_ * OS_);
        float mu = s / n;
        float var = q / n - mu * mu;
        float sc = gamma[k0 + tid] * rsqrtf(var + 1e-5f);
        scl[tid] = sc;
        shf[tid] = beta[k0 + tid] - mu * sc;
    }
    __syncthreads();

    // stage x with BN, transposing [col][f] -> xs[k][col]: 64 cols x 8 f4
    for (int i = tid; i < COLB_ * 8; i += 224) {
        int cl = i >> 3;        // 0..63
        int k4 = i & 7;         // 0..7
        float4 v = *reinterpret_cast<const float4*>(
            g_xC + (size_t)(col0 + cl) * F_ + k0 + 4 * k4);
        xs[(4 * k4 + 0) * 68 + cl] = fmaf(v.x, scl[4 * k4 + 0], shf[4 * k4 + 0]);
        xs[(4 * k4 + 1) * 68 + cl] = fmaf(v.y, scl[4 * k4 + 1], shf[4 * k4 + 1]);
        xs[(4 * k4 + 2) * 68 + cl] = fmaf(v.z, scl[4 * k4 + 2], shf[4 * k4 + 2]);
        xs[(4 * k4 + 3) * 68 + cl] = fmaf(v.w, scl[4 * k4 + 3], shf[4 * k4 + 3]);
    }
    __syncthreads();

    float a[6][2];
#pragma unroll
    for (int rr = 0; rr < 6; ++rr) { a[rr][0] = 0.f; a[rr][1] = 0.f; }

    const float4* wr4 = reinterpret_cast<const float4*>(ws + (ty * 6) * KSL_);
#pragma unroll
    for (int k4 = 0; k4 < 8; ++k4) {
        float2 xv0 = *reinterpret_cast<const float2*>(xs + (4 * k4 + 0) * 68 + 2 * lane);
        float2 xv1 = *reinterpret_cast<const float2*>(xs + (4 * k4 + 1) * 68 + 2 * lane);
        float2 xv2 = *reinterpret_cast<const float2*>(xs + (4 * k4 + 2) * 68 + 2 * lane);
        float2 xv3 = *reinterpret_cast<const float2*>(xs + (4 * k4 + 3) * 68 + 2 * lane);
#pragma unroll
        for (int rr = 0; rr < 6; ++rr) {
            float4 wv = wr4[rr * 8 + k4];
            a[rr][0] = fmaf(wv.x, xv0.x, a[rr][0]);
            a[rr][1] = fmaf(wv.x, xv0.y, a[rr][1]);
            a[rr][0] = fmaf(wv.y, xv1.x, a[rr][0]);
            a[rr][1] = fmaf(wv.y, xv1.y, a[rr][1]);
            a[rr][0] = fmaf(wv.z, xv2.x, a[rr][0]);
            a[rr][1] = fmaf(wv.z, xv2.y, a[rr][1]);
            a[rr][0] = fmaf(wv.w, xv3.x, a[rr][0]);
            a[rr][1] = fmaf(wv.w, xv3.y, a[rr][1]);
        }
    }

#pragma unroll
    for (int rr = 0; rr < 6; ++rr) {
        int r = ty * 6 + rr;
        float2 v = make_float2(a[rr][0], a[rr][1]);
        *reinterpret_cast<float2*>(
            g_p1 + (size_t)(blockIdx.y * OF_ + r) * NCOL_ + col0 + 2 * lane) = v;
    }
}

// ============================================================
// Kernel 4: layers 2..5 + head + softmax. block = batch, 320 thr.
// c1 reduced from g_p1 partials during staging (bias+relu here).
// ============================================================
#define R_DBS 212
#define R_DB  (OS_ * R_DBS)        // 4240
#define R_W2  0
#define R_W3  (48 * 44)            // 2112
#define R_W4  (R_W3 + 48 * 84)     // 6144
#define R_W5  (R_W4 + 48 * 132)    // 12480
#define R_WTOT (R_W5 + 48 * 172)   // 20736
#define R_FLOATS (R_DB + R_WTOT + 16)   // 24992

__device__ __forceinline__ void rest_layer(const float* __restrict__ bg,
                                           float* db, const float* wsl,
                                           int S, int INP, int OB,
                                           int tx, int ty) {
    float a[3] = {0.f, 0.f, 0.f};
    const float* xc = db + tx * R_DBS;
    for (int i4 = 0; i4 < INP; i4 += 4) {
        float4 xv = *reinterpret_cast<const float4*>(xc + i4);
#pragma unroll
        for (int rr = 0; rr < 3; ++rr) {
            float4 wv = *reinterpret_cast<const float4*>(wsl + (ty + 16 * rr) * S + i4);
            a[rr] = fmaf(wv.x, xv.x, a[rr]);
            a[rr] = fmaf(wv.y, xv.y, a[rr]);
            a[rr] = fmaf(wv.z, xv.z, a[rr]);
            a[rr] = fmaf(wv.w, xv.w, a[rr]);
        }
    }
    __syncthreads();
#pragma unroll
    for (int rr = 0; rr < 3; ++rr) {
        int r = ty + 16 * rr;
        if (r < OF_)
            db[tx * R_DBS + OB + r] = fmaxf(a[rr] + bg[r], 0.f);
    }
    __syncthreads();
}

__global__ void __launch_bounds__(320, 1)
k_rest(const float* __restrict__ b1,
       const float* __restrict__ W2, const float* __restrict__ b2,
       const float* __restrict__ W3, const float* __restrict__ b3,
       const float* __restrict__ W4, const float* __restrict__ b4,
       const float* __restrict__ W5, const float* __restrict__ b5,
       const float* __restrict__ Wlin, const float* __restrict__ blin,
       float* __restrict__ out) {
    extern __shared__ float sm[];
    float* db = sm;                // [j 20][chan stride 212]
    float* ws = sm + R_DB;
    float* lg = sm + R_DB + R_WTOT;

    const int tid  = threadIdx.x;
    const int lane = tid & 31;
    const int warp = tid >> 5;     // 0..9
    const int tx   = tid >> 4;     // 0..19 (col)
    const int ty   = tid & 15;     // 0..15 (row group)
    const int b    = blockIdx.x;

    for (int i = tid; i < R_FLOATS; i += 320) sm[i] = 0.f;
    __syncthreads();

    // stage c1: reduce K-split partials + bias + relu
    for (int idx = tid; idx < OF_ * OS_; idx += 320) {
        int chan = idx / OS_;
        int j = idx - chan * OS_;
        const float* pp = g_p1 + (size_t)chan * NCOL_ + b * OS_ + j;
        float s = 0.f;
#pragma unroll
        for (int p = 0; p < KSPLIT_; ++p)
            s += pp[(size_t)p * (OF_ * NCOL_)];
        db[j * R_DBS + chan] = fmaxf(s + b1[chan], 0.f);
    }
    // stage weights zero-padded
    for (int idx = tid; idx < OF_ * 42; idx += 320) {
        int o = idx / 42, i = idx - o * 42;
        ws[R_W2 + o * 44 + i] = W2[idx];
    }
    for (int idx = tid; idx < OF_ * 84; idx += 320) {
        int o = idx / 84, i = idx - o * 84;
        ws[R_W3 + o * 84 + i] = W3[idx];
    }
    for (int idx = tid; idx < OF_ * 126; idx += 320) {
        int o = idx / 126, i = idx - o * 126;
        ws[R_W4 + o * 132 + i] = W4[idx];
    }
    for (int idx = tid; idx < OF_ * 168; idx += 320) {
        int o = idx / 168, i = idx - o * 168;
        ws[R_W5 + o * 172 + i] = W5[idx];
    }
    __syncthreads();

    rest_layer(b2, db, ws + R_W2,  44,  44,  42, tx, ty);
    rest_layer(b3, db, ws + R_W3,  84,  84,  84, tx, ty);
    rest_layer(b4, db, ws + R_W4, 132, 128, 126, tx, ty);
    rest_layer(b5, db, ws + R_W5, 172, 168, 168, tx, ty);

    // head: warp n -> class n; flat k = ch*20 + j
    if (warp < NC_) {
        const float* wl = Wlin + (size_t)warp * (210 * OS_);
        float acc = 0.f;
        for (int k = lane; k < 210 * OS_; k += 32) {
            int ch = k / OS_;
            int j  = k - ch * OS_;
            acc = fmaf(wl[k], db[j * R_DBS + ch], acc);
        }
#pragma unroll
        for (int off = 16; off > 0; off >>= 1)
            acc += __shfl_xor_sync(0xffffffffu, acc, off);
        if (lane == 0) lg[warp] = acc + blin[warp];
    }
    __syncthreads();

    if (tid == 0) {
        float m = lg[0];
#pragma unroll
        for (int n = 1; n < NC_; ++n) m = fmaxf(m, lg[n]);
        float e[NC_], s = 0.f;
#pragma unroll
        for (int n = 0; n < NC_; ++n) { e[n] = __expf(lg[n] - m); s += e[n]; }
        float invs = 1.f / s;
#pragma unroll
        for (int n = 0; n < NC_; ++n) out[b * NC_ + n] = e[n] * invs;
    }
}

// ============================================================
extern "C" void kernel_launch(void* const* d_in, const int* in_sizes, int n_in,
                              void* d_out, int out_size) {
    const float* y       = (const float*)d_in[0];
    const int*   lengths = (const int*)  d_in[1];
    const float* gamma   = (const float*)d_in[2];
    const float* beta    = (const float*)d_in[3];
    const float* W1 = (const float*)d_in[4];
    const float* b1 = (const float*)d_in[5];
    const float* W2 = (const float*)d_in[6];
    const float* b2 = (const float*)d_in[7];
    const float* W3 = (const float*)d_in[8];
    const float* b3 = (const float*)d_in[9];
    const float* W4 = (const float*)d_in[10];
    const float* b4 = (const float*)d_in[11];
    const float* W5 = (const float*)d_in[12];
    const float* b5 = (const float*)d_in[13];
    const float* Wlin = (const float*)d_in[14];
    const float* blin = (const float*)d_in[15];
    float* out = (float*)d_out;

    const size_t rs_smem = (size_t)R_FLOATS * sizeof(float);    // ~100 KB
    cudaFuncSetAttribute(k_rest, cudaFuncAttributeMaxDynamicSharedMemorySize,
                         (int)rs_smem);

    dim3 g1(NCHUNK_, B_);
    k_pool_partial<<<g1, 128>>>(y, lengths);
    k_pool_finish<<<B_, 512>>>(y, lengths);
    dim3 gl1(NCOL_ / COLB_, KSPLIT_);
    k_l1<<<gl1, 224>>>(W1, gamma, beta);
    k_rest<<<B_, 320, rs_smem>>>(b1, W2, b2, W3, b3, W4, b4, W5, b5,
                                 Wlin, blin, out);
}

// round 13
// speedup vs baseline: 1.0750x; 1.0750x over previous
#include <cuda_runtime.h>
#include <cuda_bf16.h>
#include <math.h>

// Problem constants
#define B_   128
#define T_   2048
#define F_   512
#define OS_  20
#define OF_  42
#define NC_  10
#define NCHUNK_ 8
#define CHUNK_  256   // NCHUNK_*CHUNK_ == T_
#define NCOL_ (B_ * OS_)   // 2560
#define KSPLIT_ 8
#define KSL_ (F_ / KSPLIT_)   // 64
#define COLB_ 64

// -------- device scratch (no allocation allowed) --------
__device__ float g_partial[B_ * NCHUNK_ * F_];    // 2 MB
__device__ float g_xC[NCOL_ * F_];                // [col][f]
__device__ float g_p1[KSPLIT_ * OF_ * NCOL_];     // l1 K-split partials (3.4MB)
__device__ float g_bns[B_ * F_];
__device__ float g_bnss[B_ * F_];
__device__ float g_scale[F_];
__device__ float g_shift[F_];

// ============================================================
// Kernel 1: partial column sums of y over t in [chunk] ∩ [0, fs)
// ============================================================
__global__ void k_pool_partial(const float* __restrict__ y,
                               const int*   __restrict__ lengths) {
    const int c = blockIdx.x;
    const int b = blockIdx.y;
    const int tid = threadIdx.x;

    const int fs = lengths[b] - (OS_ - 1);
    int t0 = c * CHUNK_;
    int t1 = min(t0 + CHUNK_, fs);

    const float4* row = reinterpret_cast<const float4*>(y + (size_t)b * T_ * F_);
    const int rstride = F_ / 4;

    float4 acc = make_float4(0.f, 0.f, 0.f, 0.f);
    int t = t0;
    for (; t + 8 <= t1; t += 8) {
        float4 v0 = __ldcs(&row[(t + 0) * rstride + tid]);
        float4 v1 = __ldcs(&row[(t + 1) * rstride + tid]);
        float4 v2 = __ldcs(&row[(t + 2) * rstride + tid]);
        float4 v3 = __ldcs(&row[(t + 3) * rstride + tid]);
        float4 v4 = __ldcs(&row[(t + 4) * rstride + tid]);
        float4 v5 = __ldcs(&row[(t + 5) * rstride + tid]);
        float4 v6 = __ldcs(&row[(t + 6) * rstride + tid]);
        float4 v7 = __ldcs(&row[(t + 7) * rstride + tid]);
        acc.x += v0.x; acc.y += v0.y; acc.z += v0.z; acc.w += v0.w;
        acc.x += v1.x; acc.y += v1.y; acc.z += v1.z; acc.w += v1.w;
        acc.x += v2.x; acc.y += v2.y; acc.z += v2.z; acc.w += v2.w;
        acc.x += v3.x; acc.y += v3.y; acc.z += v3.z; acc.w += v3.w;
        acc.x += v4.x; acc.y += v4.y; acc.z += v4.z; acc.w += v4.w;
        acc.x += v5.x; acc.y += v5.y; acc.z += v5.z; acc.w += v5.w;
        acc.x += v6.x; acc.y += v6.y; acc.z += v6.z; acc.w += v6.w;
        acc.x += v7.x; acc.y += v7.y; acc.z += v7.z; acc.w += v7.w;
    }
    for (; t < t1; ++t) {
        float4 v = __ldcs(&row[t * rstride + tid]);
        acc.x += v.x; acc.y += v.y; acc.z += v.z; acc.w += v.w;
    }

    float4* out = reinterpret_cast<float4*>(g_partial + (size_t)(b * NCHUNK_ + c) * F_);
    out[tid] = acc;
}

// ============================================================
// Kernel 2: finish pooling -> g_xC[col][f] (coalesced) + BN partials.
// ============================================================
__global__ void __launch_bounds__(512, 1)
k_pool_finish(const float* __restrict__ y,
              const int*   __restrict__ lengths) {
    const int b = blockIdx.x;
    const int f = threadIdx.x;

    const int fs = lengths[b] - (OS_ - 1);
    const float inv = 1.0f / (float)fs;

    float base = 0.f;
#pragma unroll
    for (int c = 0; c < NCHUNK_; ++c)
        base += g_partial[(size_t)(b * NCHUNK_ + c) * F_ + f];

    const float* yb = y + (size_t)b * T_ * F_ + f;

    float vals[OS_];
    float run = base;
    float s = 0.f, ss = 0.f;
    vals[0] = run * inv;
    s += vals[0]; ss = fmaf(vals[0], vals[0], ss);
#pragma unroll
    for (int j = 1; j < OS_; ++j) {
        run += yb[(size_t)(fs + j - 1) * F_] - yb[(size_t)(j - 1) * F_];
        float v = run * inv;
        vals[j] = v;
        s += v; ss = fmaf(v, v, ss);
    }
    g_bns [b * F_ + f] = s;
    g_bnss[b * F_ + f] = ss;

#pragma unroll
    for (int j = 0; j < OS_; ++j)
        g_xC[(size_t)(b * OS_ + j) * F_ + f] = vals[j];
}

// ============================================================
// Kernel 3: BN stats reduce -> fused scale/shift.
// ============================================================
__global__ void k_bnstats(const float* __restrict__ gamma,
                          const float* __restrict__ beta) {
    const int f = blockIdx.x;
    const int b = threadIdx.x;

    __shared__ float s1[128];
    __shared__ float s2[128];

    s1[b] = g_bns [b * F_ + f];
    s2[b] = g_bnss[b * F_ + f];
    __syncthreads();
    for (int off = 64; off > 0; off >>= 1) {
        if (b < off) { s1[b] += s1[b + off]; s2[b] += s2[b + off]; }
        __syncthreads();
    }
    if (b == 0) {
        const float n = (float)(B_ * OS_);
        float mu = s1[0] / n;
        float var = s2[0] / n - mu * mu;
        float sc = gamma[f] * rsqrtf(var + 1e-5f);
        g_scale[f] = sc;
        g_shift[f] = beta[f] - mu * sc;
    }
}

// ============================================================
// Kernel 4: layer 1 GEMM (R8 config: KSPLIT 8, block 224, 2/SM).
// ============================================================
__global__ void __launch_bounds__(224, 2)
k_l1(const float* __restrict__ W1) {
    __shared__ float ws[OF_ * KSL_];       // [r][k] 42x64
    __shared__ float xs[KSL_ * 68];        // [k][col], stride 68

    const int tid  = threadIdx.x;
    const int lane = tid & 31;
    const int ty   = tid >> 5;             // 0..6
    const int col0 = blockIdx.x * COLB_;
    const int k0   = blockIdx.y * KSL_;

    // stage W slice (42 x 16 float4)
    {
        const float4* wg = reinterpret_cast<const float4*>(W1);
        float4* wsm = reinterpret_cast<float4*>(ws);
        for (int i = tid; i < OF_ * 16; i += 224) {
            int r = i >> 4, k4 = i & 15;
            wsm[r * 16 + k4] = wg[r * 128 + (k0 >> 2) + k4];
        }
    }
    // stage x with BN, transposing [col][f] -> xs[k][col]: 64 cols x 16 f4
    for (int i = tid; i < COLB_ * 16; i += 224) {
        int cl = i >> 4;        // 0..63
        int k4 = i & 15;        // 0..15
        float4 v = *reinterpret_cast<const float4*>(
            g_xC + (size_t)(col0 + cl) * F_ + k0 + 4 * k4);
        float4 sc = *reinterpret_cast<const float4*>(g_scale + k0 + 4 * k4);
        float4 sh = *reinterpret_cast<const float4*>(g_shift + k0 + 4 * k4);
        xs[(4 * k4 + 0) * 68 + cl] = fmaf(v.x, sc.x, sh.x);
        xs[(4 * k4 + 1) * 68 + cl] = fmaf(v.y, sc.y, sh.y);
        xs[(4 * k4 + 2) * 68 + cl] = fmaf(v.z, sc.z, sh.z);
        xs[(4 * k4 + 3) * 68 + cl] = fmaf(v.w, sc.w, sh.w);
    }
    __syncthreads();

    float a[6][2];
#pragma unroll
    for (int rr = 0; rr < 6; ++rr) { a[rr][0] = 0.f; a[rr][1] = 0.f; }

    const float4* wr4 = reinterpret_cast<const float4*>(ws + (ty * 6) * KSL_);
#pragma unroll 2
    for (int k4 = 0; k4 < 16; ++k4) {
        float2 xv0 = *reinterpret_cast<const float2*>(xs + (4 * k4 + 0) * 68 + 2 * lane);
        float2 xv1 = *reinterpret_cast<const float2*>(xs + (4 * k4 + 1) * 68 + 2 * lane);
        float2 xv2 = *reinterpret_cast<const float2*>(xs + (4 * k4 + 2) * 68 + 2 * lane);
        float2 xv3 = *reinterpret_cast<const float2*>(xs + (4 * k4 + 3) * 68 + 2 * lane);
#pragma unroll
        for (int rr = 0; rr < 6; ++rr) {
            float4 wv = wr4[rr * 16 + k4];
            a[rr][0] = fmaf(wv.x, xv0.x, a[rr][0]);
            a[rr][1] = fmaf(wv.x, xv0.y, a[rr][1]);
            a[rr][0] = fmaf(wv.y, xv1.x, a[rr][0]);
            a[rr][1] = fmaf(wv.y, xv1.y, a[rr][1]);
            a[rr][0] = fmaf(wv.z, xv2.x, a[rr][0]);
            a[rr][1] = fmaf(wv.z, xv2.y, a[rr][1]);
            a[rr][0] = fmaf(wv.w, xv3.x, a[rr][0]);
            a[rr][1] = fmaf(wv.w, xv3.y, a[rr][1]);
        }
    }

#pragma unroll
    for (int rr = 0; rr < 6; ++rr) {
        int r = ty * 6 + rr;
        float2 v = make_float2(a[rr][0], a[rr][1]);
        *reinterpret_cast<float2*>(
            g_p1 + (size_t)(blockIdx.y * OF_ + r) * NCOL_ + col0 + 2 * lane) = v;
    }
}

// ============================================================
// Kernel 5: layers 2..5 + head + softmax. block = batch, 640 thr.
// warp = one column (20 warps), lane = rows {lane, lane+32}.
// Scalar W loads at ODD strides (45/85/127/169): conflict-free.
// No zero-init, exact-size staging. smem 88.6 KB.
// ============================================================
#define R_DBS 212
#define R_DB  (OS_ * R_DBS)        // 4240
#define R_W2  0                    // stride 45
#define R_W3  (42 * 45)            // 1890, stride 85
#define R_W4  (R_W3 + 42 * 85)     // 5460, stride 127
#define R_W5  (R_W4 + 42 * 127)    // 10794, stride 169
#define R_WTOT (R_W5 + 42 * 169)   // 17892
#define R_FLOATS (R_DB + R_WTOT + 32)   // 22164

__device__ __forceinline__ void rest_layer(const float* __restrict__ bg,
                                           float* db, const float* wsl,
                                           int S, int IN, int OB,
                                           int col, int lane) {
    const bool has1 = (lane < 10);
    const float* xc = db + col * R_DBS;
    const float* w0 = wsl + lane * S;
    const float* w1 = wsl + (has1 ? lane + 32 : lane) * S;

    float a0 = 0.f, a1 = 0.f, b0 = 0.f, b1v = 0.f;
    int i = 0;
    for (; i + 2 <= IN; i += 2) {
        float x0 = xc[i];
        float x1 = xc[i + 1];
        a0  = fmaf(w0[i],     x0, a0);
        a1  = fmaf(w1[i],     x0, a1);
        b0  = fmaf(w0[i + 1], x1, b0);
        b1v = fmaf(w1[i + 1], x1, b1v);
    }
    if (i < IN) {
        float x0 = xc[i];
        a0 = fmaf(w0[i], x0, a0);
        a1 = fmaf(w1[i], x0, a1);
    }
    a0 += b0; a1 += b1v;
    __syncthreads();
    db[col * R_DBS + OB + lane] = fmaxf(a0 + bg[lane], 0.f);
    if (has1)
        db[col * R_DBS + OB + lane + 32] = fmaxf(a1 + bg[lane + 32], 0.f);
    __syncthreads();
}

__global__ void __launch_bounds__(640, 1)
k_rest(const float* __restrict__ b1,
       const float* __restrict__ W2, const float* __restrict__ b2,
       const float* __restrict__ W3, const float* __restrict__ b3,
       const float* __restrict__ W4, const float* __restrict__ b4,
       const float* __restrict__ W5, const float* __restrict__ b5,
       const float* __restrict__ Wlin, const float* __restrict__ blin,
       float* __restrict__ out) {
    extern __shared__ float sm[];
    float* db = sm;                // [col 20][chan stride 212]
    float* ws = sm + R_DB;
    float* lg = sm + R_DB + R_WTOT;  // 32: lg2[20] partials

    const int tid  = threadIdx.x;
    const int lane = tid & 31;
    const int warp = tid >> 5;     // 0..19 (= column)
    const int b    = blockIdx.x;

    // stage c1: reduce K-split partials + bias + relu (840 elems)
    for (int idx = tid; idx < OF_ * OS_; idx += 640) {
        int chan = idx / OS_;
        int j = idx - chan * OS_;
        const float* pp = g_p1 + (size_t)chan * NCOL_ + b * OS_ + j;
        float s = 0.f;
#pragma unroll
        for (int p = 0; p < KSPLIT_; ++p)
            s += pp[(size_t)p * (OF_ * NCOL_)];
        db[j * R_DBS + chan] = fmaxf(s + b1[chan], 0.f);
    }
    // stage weights, exact size, odd strides
    for (int idx = tid; idx < OF_ * 42; idx += 640) {
        int o = idx / 42, i = idx - o * 42;
        ws[R_W2 + o * 45 + i] = W2[idx];
    }
    for (int idx = tid; idx < OF_ * 84; idx += 640) {
        int o = idx / 84, i = idx - o * 84;
        ws[R_W3 + o * 85 + i] = W3[idx];
    }
    for (int idx = tid; idx < OF_ * 126; idx += 640) {
        int o = idx / 126, i = idx - o * 126;
        ws[R_W4 + o * 127 + i] = W4[idx];
    }
    for (int idx = tid; idx < OF_ * 168; idx += 640) {
        int o = idx / 168, i = idx - o * 168;
        ws[R_W5 + o * 169 + i] = W5[idx];
    }
    __syncthreads();

    rest_layer(b2, db, ws + R_W2,  45,  42,  42, warp, lane);
    rest_layer(b3, db, ws + R_W3,  85,  84,  84, warp, lane);
    rest_layer(b4, db, ws + R_W4, 127, 126, 126, warp, lane);
    rest_layer(b5, db, ws + R_W5, 169, 168, 168, warp, lane);

    // head: warp w -> class w>>1, K-half w&1. k = lane + 32*half, step 64.
    {
        const int cls  = warp >> 1;
        const int half = warp & 1;
        const float* wl = Wlin + (size_t)cls * (210 * OS_);
        float acc = 0.f;
        for (int k = lane + 32 * half; k < 210 * OS_; k += 64) {
            int ch = k / OS_;
            int j  = k - ch * OS_;
            acc = fmaf(wl[k], db[j * R_DBS + ch], acc);
        }
#pragma unroll
        for (int off = 16; off > 0; off >>= 1)
            acc += __shfl_xor_sync(0xffffffffu, acc, off);
        if (lane == 0) lg[warp] = acc;   // lg[cls*2+half]
    }
    __syncthreads();

    if (tid == 0) {
        float l[NC_];
#pragma unroll
        for (int n = 0; n < NC_; ++n) l[n] = lg[2 * n] + lg[2 * n + 1] + blin[n];
        float m = l[0];
#pragma unroll
        for (int n = 1; n < NC_; ++n) m = fmaxf(m, l[n]);
        float e[NC_], s = 0.f;
#pragma unroll
        for (int n = 0; n < NC_; ++n) { e[n] = __expf(l[n] - m); s += e[n]; }
        float invs = 1.f / s;
#pragma unroll
        for (int n = 0; n < NC_; ++n) out[b * NC_ + n] = e[n] * invs;
    }
}

// ============================================================
extern "C" void kernel_launch(void* const* d_in, const int* in_sizes, int n_in,
                              void* d_out, int out_size) {
    const float* y       = (const float*)d_in[0];
    const int*   lengths = (const int*)  d_in[1];
    const float* gamma   = (const float*)d_in[2];
    const float* beta    = (const float*)d_in[3];
    const float* W1 = (const float*)d_in[4];
    const float* b1 = (const float*)d_in[5];
    const float* W2 = (const float*)d_in[6];
    const float* b2 = (const float*)d_in[7];
    const float* W3 = (const float*)d_in[8];
    const float* b3 = (const float*)d_in[9];
    const float* W4 = (const float*)d_in[10];
    const float* b4 = (const float*)d_in[11];
    const float* W5 = (const float*)d_in[12];
    const float* b5 = (const float*)d_in[13];
    const float* Wlin = (const float*)d_in[14];
    const float* blin = (const float*)d_in[15];
    float* out = (float*)d_out;

    const size_t rs_smem = (size_t)R_FLOATS * sizeof(float);    // ~88.7 KB
    cudaFuncSetAttribute(k_rest, cudaFuncAttributeMaxDynamicSharedMemorySize,
                         (int)rs_smem);

    dim3 g1(NCHUNK_, B_);
    k_pool_partial<<<g1, 128>>>(y, lengths);
    k_pool_finish<<<B_, 512>>>(y, lengths);
    k_bnstats<<<F_, 128>>>(gamma, beta);
    dim3 gl1(NCOL_ / COLB_, KSPLIT_);
    k_l1<<<gl1, 224>>>(W1);
    k_rest<<<B_, 640, rs_smem>>>(b1, W2, b2, W3, b3, W4, b4, W5, b5,
                                 Wlin, blin, out);
}